// round 7
// baseline (speedup 1.0000x reference)
#include <cuda_runtime.h>

#define HH 512
#define WW 512
#define BB 8
#define PLANE (HH * WW)
#define CPW 24       // output columns per warp (32 lanes - 8 halo)
#define SEG 32       // output rows swept per warp
#define STEPS (SEG + 4)
#define NWARP 4
#define NTHR (NWARP * 32)

__device__ __forceinline__ int refl(int q, int n) {
    if (q < 0) q = -q;
    if (q >= n) q = 2 * n - 2 - q;
    return q;
}

// Horizontal 5-tap sum across warp lanes (lane = column): 3 shuffles + 3 adds.
__device__ __forceinline__ float hsum5(float v) {
    const unsigned m = 0xffffffffu;
    float s1 = v + __shfl_down_sync(m, v, 1);
    return __shfl_up_sync(m, s1, 2) + s1 + __shfl_down_sync(m, v, 2);
}

struct Row6 { float g0, g1, g2, p0, p1, p2; };

__device__ __forceinline__ Row6 load6(const float* __restrict__ gb,
                                      const float* __restrict__ pb, int o) {
    Row6 r;
    r.g0 = __ldg(gb + o); r.g1 = __ldg(gb + o + PLANE); r.g2 = __ldg(gb + o + 2 * PLANE);
    r.p0 = __ldg(pb + o); r.p1 = __ldg(pb + o + PLANE); r.p2 = __ldg(pb + o + 2 * PLANE);
    return r;
}

template<bool ADD>
__device__ __forceinline__ void apply6(float vs[21], const Row6& r) {
    const float s = ADD ? 1.f : -1.f;
    const float sg0 = s * r.g0, sg1 = s * r.g1, sg2 = s * r.g2;
    const float sp0 = s * r.p0, sp1 = s * r.p1, sp2 = s * r.p2;
    vs[0] += sg0; vs[1] += sg1; vs[2] += sg2;
    vs[3] += sp0; vs[4] += sp1; vs[5] += sp2;
    vs[6]  = fmaf(sg0, r.g0, vs[6]);  vs[7]  = fmaf(sg0, r.g1, vs[7]);  vs[8]  = fmaf(sg0, r.g2, vs[8]);
    vs[9]  = fmaf(sg1, r.g1, vs[9]);  vs[10] = fmaf(sg1, r.g2, vs[10]); vs[11] = fmaf(sg2, r.g2, vs[11]);
    vs[12] = fmaf(sg0, r.p0, vs[12]); vs[13] = fmaf(sg0, r.p1, vs[13]); vs[14] = fmaf(sg0, r.p2, vs[14]);
    vs[15] = fmaf(sg1, r.p0, vs[15]); vs[16] = fmaf(sg1, r.p1, vs[16]); vs[17] = fmaf(sg1, r.p2, vs[17]);
    vs[18] = fmaf(sg2, r.p0, vs[18]); vs[19] = fmaf(sg2, r.p1, vs[19]); vs[20] = fmaf(sg2, r.p2, vs[20]);
}

__global__ __launch_bounds__(NTHR, 4)
void gf_fused(const float* __restrict__ gd, const float* __restrict__ pd,
              float* __restrict__ out) {
    // 5-row history of horizontally-summed a/b, lane-indexed (conflict-free).
    __shared__ float ring[5][12][NTHR];

    const int b = blockIdx.z;
    const int lane = threadIdx.x & 31;
    const int warp = threadIdx.x >> 5;
    const int tid = threadIdx.x;
    const int tile = blockIdx.x * NWARP + warp;
    const int x0 = tile * CPW;
    if (x0 >= WW) return;                      // warp-uniform
    const int x = x0 - 4 + lane;               // this lane's column
    const int xr = refl(x, WW);
    const int y0 = blockIdx.y * SEG;

    const float* gb = gd + b * 3 * PLANE + xr;
    const float* pb = pd + b * 3 * PLANE + xr;

    float vs[21];
#pragma unroll
    for (int k = 0; k < 21; k++) vs[k] = 0.f;

    // Zero this thread's ring slots and the running vertical sum.
#pragma unroll
    for (int s = 0; s < 5; s++)
#pragma unroll
        for (int k = 0; k < 12; k++) ring[s][k][tid] = 0.f;

    float M[12];
#pragma unroll
    for (int k = 0; k < 12; k++) M[k] = 0.f;

    // Preload product window rows refl(y0-4 .. y0-1).
#pragma unroll
    for (int dy = -4; dy < 0; dy++) {
        Row6 r = load6(gb, pb, refl(y0 + dy, HH) * WW);
        apply6<true>(vs, r);
    }

    const bool ovalid = (lane >= 4) && (lane < 28) && (x < WW);
    const float* gout = gd + b * 3 * PLANE + x; // guidance at true column
    float* ob = out + b * 3 * PLANE + x;
    const float inv = 1.0f / 25.0f;
    const float eps = 1e-4f;

    for (int chunk = 0; chunk < STEPS; chunk += 5) {
#pragma unroll
        for (int ph = 0; ph < 5; ph++) {        // slot index == st % 5 == ph
            const int st = chunk + ph;
            if (st < STEPS) {
                const int r = y0 - 2 + st;      // ab-row being produced
                Row6 radd = load6(gb, pb, refl(r + 2, HH) * WW);
                Row6 rsub = load6(gb, pb, refl(r - 2, HH) * WW);
                apply6<true>(vs, radd);

                float m[21];
#pragma unroll
                for (int k = 0; k < 21; k++) m[k] = hsum5(vs[k]);

                const float mI0 = m[0] * inv, mI1 = m[1] * inv, mI2 = m[2] * inv;
                const float mp0 = m[3] * inv, mp1 = m[4] * inv, mp2 = m[5] * inv;

                const float a00 = m[6]  * inv - mI0 * mI0 + eps;
                const float a01 = m[7]  * inv - mI0 * mI1;
                const float a02 = m[8]  * inv - mI0 * mI2;
                const float a11 = m[9]  * inv - mI1 * mI1 + eps;
                const float a12 = m[10] * inv - mI1 * mI2;
                const float a22 = m[11] * inv - mI2 * mI2 + eps;

                const float c00 = m[12] * inv - mI0 * mp0, c01 = m[13] * inv - mI0 * mp1, c02 = m[14] * inv - mI0 * mp2;
                const float c10 = m[15] * inv - mI1 * mp0, c11 = m[16] * inv - mI1 * mp1, c12 = m[17] * inv - mI1 * mp2;
                const float c20 = m[18] * inv - mI2 * mp0, c21 = m[19] * inv - mI2 * mp1, c22 = m[20] * inv - mI2 * mp2;

                float i00 = a11 * a22 - a12 * a12;
                float i01 = a02 * a12 - a01 * a22;
                float i02 = a01 * a12 - a02 * a11;
                float i11 = a00 * a22 - a02 * a02;
                float i12 = a01 * a02 - a00 * a12;
                float i22 = a00 * a11 - a01 * a01;
                const float det = a00 * i00 + a01 * i01 + a02 * i02;
                const float rd = 1.0f / det;
                i00 *= rd; i01 *= rd; i02 *= rd; i11 *= rd; i12 *= rd; i22 *= rd;

                float ab[12];
                ab[0]  = i00 * c00 + i01 * c10 + i02 * c20;   // A00
                ab[1]  = i00 * c01 + i01 * c11 + i02 * c21;   // A01
                ab[2]  = i00 * c02 + i01 * c12 + i02 * c22;   // A02
                ab[3]  = i01 * c00 + i11 * c10 + i12 * c20;   // A10
                ab[4]  = i01 * c01 + i11 * c11 + i12 * c21;   // A11
                ab[5]  = i01 * c02 + i11 * c12 + i12 * c22;   // A12
                ab[6]  = i02 * c00 + i12 * c10 + i22 * c20;   // A20
                ab[7]  = i02 * c01 + i12 * c11 + i22 * c21;   // A21
                ab[8]  = i02 * c02 + i12 * c12 + i22 * c22;   // A22
                ab[9]  = mp0 - (ab[0] * mI0 + ab[3] * mI1 + ab[6] * mI2);  // b0
                ab[10] = mp1 - (ab[1] * mI0 + ab[4] * mI1 + ab[7] * mI2);  // b1
                ab[11] = mp2 - (ab[2] * mI0 + ab[5] * mI1 + ab[8] * mI2);  // b2

                // Horizontal 5-tap of a/b; update running vertical sum via smem ring.
#pragma unroll
                for (int k = 0; k < 12; k++) {
                    const float h = hsum5(ab[k]);
                    M[k] += h - ring[ph][k][tid];
                    ring[ph][k][tid] = h;
                }

                const int yout = r - 2;
                if (st >= 4 && ovalid) {        // M holds rows yout-2..yout+2
                    const int o = yout * WW;
                    const float g0 = __ldg(gout + o);
                    const float g1 = __ldg(gout + o + PLANE);
                    const float g2 = __ldg(gout + o + 2 * PLANE);
                    ob[o]             = (g0 * M[0] + g1 * M[3] + g2 * M[6] + M[9])  * inv;
                    ob[o + PLANE]     = (g0 * M[1] + g1 * M[4] + g2 * M[7] + M[10]) * inv;
                    ob[o + 2 * PLANE] = (g0 * M[2] + g1 * M[5] + g2 * M[8] + M[11]) * inv;
                }

                apply6<false>(vs, rsub);
            }
        }
    }
}

extern "C" void kernel_launch(void* const* d_in, const int* in_sizes, int n_in,
                              void* d_out, int out_size) {
    const float* gd = (const float*)d_in[0];
    const float* pd = (const float*)d_in[1];
    float* out = (float*)d_out;

    const int tiles = (WW + CPW - 1) / CPW;            // 22
    const int gx = (tiles + NWARP - 1) / NWARP;        // 6
    dim3 grid(gx, HH / SEG, BB);
    dim3 blk(NTHR);
    gf_fused<<<grid, blk>>>(gd, pd, out);
}

// round 8
// speedup vs baseline: 1.5130x; 1.5130x over previous
#include <cuda_runtime.h>
#include <cuda_fp16.h>

#define HH 512
#define WW 512
#define BB 8
#define PLANE (HH * WW)
#define CPW 24       // output columns per warp (32 lanes - 8 halo)
#define SEG 43       // output rows per block (12 blocks cover 512, last masked)
#define GY 12
#define STEPS (SEG + 4)
#define NWARP 4
#define NTHR (NWARP * 32)

__device__ __forceinline__ int refl(int q, int n) {
    if (q < 0) q = -q;
    if (q >= n) q = 2 * n - 2 - q;
    return q;
}

// Horizontal 5-tap sum across warp lanes (lane = column): 3 shuffles + 3 adds.
__device__ __forceinline__ float hsum5(float v) {
    const unsigned m = 0xffffffffu;
    float s1 = v + __shfl_down_sync(m, v, 1);
    return __shfl_up_sync(m, s1, 2) + s1 + __shfl_down_sync(m, v, 2);
}

struct Row6 { float g0, g1, g2, p0, p1, p2; };

__device__ __forceinline__ Row6 load6(const float* __restrict__ gb,
                                      const float* __restrict__ pb, int o) {
    Row6 r;
    r.g0 = __ldg(gb + o); r.g1 = __ldg(gb + o + PLANE); r.g2 = __ldg(gb + o + 2 * PLANE);
    r.p0 = __ldg(pb + o); r.p1 = __ldg(pb + o + PLANE); r.p2 = __ldg(pb + o + 2 * PLANE);
    return r;
}

template<bool ADD>
__device__ __forceinline__ void apply6(float vs[21], const Row6& r) {
    const float s = ADD ? 1.f : -1.f;
    const float sg0 = s * r.g0, sg1 = s * r.g1, sg2 = s * r.g2;
    const float sp0 = s * r.p0, sp1 = s * r.p1, sp2 = s * r.p2;
    vs[0] += sg0; vs[1] += sg1; vs[2] += sg2;
    vs[3] += sp0; vs[4] += sp1; vs[5] += sp2;
    vs[6]  = fmaf(sg0, r.g0, vs[6]);  vs[7]  = fmaf(sg0, r.g1, vs[7]);  vs[8]  = fmaf(sg0, r.g2, vs[8]);
    vs[9]  = fmaf(sg1, r.g1, vs[9]);  vs[10] = fmaf(sg1, r.g2, vs[10]); vs[11] = fmaf(sg2, r.g2, vs[11]);
    vs[12] = fmaf(sg0, r.p0, vs[12]); vs[13] = fmaf(sg0, r.p1, vs[13]); vs[14] = fmaf(sg0, r.p2, vs[14]);
    vs[15] = fmaf(sg1, r.p0, vs[15]); vs[16] = fmaf(sg1, r.p1, vs[16]); vs[17] = fmaf(sg1, r.p2, vs[17]);
    vs[18] = fmaf(sg2, r.p0, vs[18]); vs[19] = fmaf(sg2, r.p1, vs[19]); vs[20] = fmaf(sg2, r.p2, vs[20]);
}

__global__ __launch_bounds__(NTHR, 4)
void gf_fused(const float* __restrict__ gd, const float* __restrict__ pd,
              float* __restrict__ out) {
    const int b = blockIdx.z;
    const int lane = threadIdx.x & 31;
    const int warp = threadIdx.x >> 5;
    const int tile = blockIdx.x * NWARP + warp;
    const int x0 = tile * CPW;
    if (x0 >= WW) return;                      // warp-uniform
    const int x = x0 - 4 + lane;               // this lane's column
    const int xr = refl(x, WW);
    const int y0 = blockIdx.y * SEG;

    const float* gb = gd + b * 3 * PLANE + xr;
    const float* pb = pd + b * 3 * PLANE + xr;

    float vs[21];
#pragma unroll
    for (int k = 0; k < 21; k++) vs[k] = 0.f;

    // 5-row history of h-summed a/b, half2-packed (channel pairs) in registers.
    __half2 ring[5][6];
#pragma unroll
    for (int s = 0; s < 5; s++)
#pragma unroll
        for (int k = 0; k < 6; k++) ring[s][k] = __float2half2_rn(0.f);

    float M[12];                                // running vertical sum of h
#pragma unroll
    for (int k = 0; k < 12; k++) M[k] = 0.f;

    // Preload product window rows refl(y0-4 .. y0-1).
#pragma unroll
    for (int dy = -4; dy < 0; dy++) {
        Row6 r = load6(gb, pb, refl(y0 + dy, HH) * WW);
        apply6<true>(vs, r);
    }

    const bool ovalid = (lane >= 4) && (lane < 28) && (x < WW);
    const float* gout = gd + b * 3 * PLANE + x; // guidance at true column
    float* ob = out + b * 3 * PLANE + x;
    const float inv = 1.0f / 25.0f;
    const float eps = 1e-4f;

    for (int chunk = 0; chunk < STEPS; chunk += 5) {
#pragma unroll
        for (int ph = 0; ph < 5; ph++) {        // ring slot == st % 5 == ph
            const int st = chunk + ph;
            if (st < STEPS) {
                const int r = y0 - 2 + st;      // ab-row being produced
                Row6 radd = load6(gb, pb, refl(r + 2, HH) * WW);
                Row6 rsub = load6(gb, pb, refl(r - 2, HH) * WW);
                apply6<true>(vs, radd);

                float m[21];
#pragma unroll
                for (int k = 0; k < 21; k++) m[k] = hsum5(vs[k]);

                const float mI0 = m[0] * inv, mI1 = m[1] * inv, mI2 = m[2] * inv;
                const float mp0 = m[3] * inv, mp1 = m[4] * inv, mp2 = m[5] * inv;

                const float a00 = m[6]  * inv - mI0 * mI0 + eps;
                const float a01 = m[7]  * inv - mI0 * mI1;
                const float a02 = m[8]  * inv - mI0 * mI2;
                const float a11 = m[9]  * inv - mI1 * mI1 + eps;
                const float a12 = m[10] * inv - mI1 * mI2;
                const float a22 = m[11] * inv - mI2 * mI2 + eps;

                const float c00 = m[12] * inv - mI0 * mp0, c01 = m[13] * inv - mI0 * mp1, c02 = m[14] * inv - mI0 * mp2;
                const float c10 = m[15] * inv - mI1 * mp0, c11 = m[16] * inv - mI1 * mp1, c12 = m[17] * inv - mI1 * mp2;
                const float c20 = m[18] * inv - mI2 * mp0, c21 = m[19] * inv - mI2 * mp1, c22 = m[20] * inv - mI2 * mp2;

                float i00 = a11 * a22 - a12 * a12;
                float i01 = a02 * a12 - a01 * a22;
                float i02 = a01 * a12 - a02 * a11;
                float i11 = a00 * a22 - a02 * a02;
                float i12 = a01 * a02 - a00 * a12;
                float i22 = a00 * a11 - a01 * a01;
                const float det = a00 * i00 + a01 * i01 + a02 * i02;
                const float rd = 1.0f / det;
                i00 *= rd; i01 *= rd; i02 *= rd; i11 *= rd; i12 *= rd; i22 *= rd;

                float ab[12];
                ab[0]  = i00 * c00 + i01 * c10 + i02 * c20;   // A00
                ab[1]  = i00 * c01 + i01 * c11 + i02 * c21;   // A01
                ab[2]  = i00 * c02 + i01 * c12 + i02 * c22;   // A02
                ab[3]  = i01 * c00 + i11 * c10 + i12 * c20;   // A10
                ab[4]  = i01 * c01 + i11 * c11 + i12 * c21;   // A11
                ab[5]  = i01 * c02 + i11 * c12 + i12 * c22;   // A12
                ab[6]  = i02 * c00 + i12 * c10 + i22 * c20;   // A20
                ab[7]  = i02 * c01 + i12 * c11 + i22 * c21;   // A21
                ab[8]  = i02 * c02 + i12 * c12 + i22 * c22;   // A22
                ab[9]  = mp0 - (ab[0] * mI0 + ab[3] * mI1 + ab[6] * mI2);  // b0
                ab[10] = mp1 - (ab[1] * mI0 + ab[4] * mI1 + ab[7] * mI2);  // b1
                ab[11] = mp2 - (ab[2] * mI0 + ab[5] * mI1 + ab[8] * mI2);  // b2

                // Horizontal 5-tap of a/b; running vertical sum with half2 ring.
#pragma unroll
                for (int k = 0; k < 6; k++) {
                    const float h0 = hsum5(ab[2 * k]);
                    const float h1 = hsum5(ab[2 * k + 1]);
                    const float2 old = __half22float2(ring[ph][k]);
                    M[2 * k]     += h0 - old.x;
                    M[2 * k + 1] += h1 - old.y;
                    ring[ph][k] = __floats2half2_rn(h0, h1);
                }

                const int yout = r - 2;
                if (st >= 4 && yout < HH && ovalid) {  // M = rows yout-2..yout+2
                    const int o = yout * WW;
                    const float g0 = __ldg(gout + o);
                    const float g1 = __ldg(gout + o + PLANE);
                    const float g2 = __ldg(gout + o + 2 * PLANE);
                    ob[o]             = (g0 * M[0] + g1 * M[3] + g2 * M[6] + M[9])  * inv;
                    ob[o + PLANE]     = (g0 * M[1] + g1 * M[4] + g2 * M[7] + M[10]) * inv;
                    ob[o + 2 * PLANE] = (g0 * M[2] + g1 * M[5] + g2 * M[8] + M[11]) * inv;
                }

                apply6<false>(vs, rsub);
            }
        }
    }
}

extern "C" void kernel_launch(void* const* d_in, const int* in_sizes, int n_in,
                              void* d_out, int out_size) {
    const float* gd = (const float*)d_in[0];
    const float* pd = (const float*)d_in[1];
    float* out = (float*)d_out;

    const int tiles = (WW + CPW - 1) / CPW;            // 22
    const int gx = (tiles + NWARP - 1) / NWARP;        // 6
    dim3 grid(gx, GY, BB);
    dim3 blk(NTHR);
    gf_fused<<<grid, blk>>>(gd, pd, out);
}